// round 7
// baseline (speedup 1.0000x reference)
#include <cuda_runtime.h>

#define NPTS   8192
#define BATCH  4
#define TPB    128
#define QTY    8                 // ty groups
#define QPT    8                 // queries per thread (packed as q / q+4)
#define QB     (QTY*QPT)         // 64 queries per block
#define NQT    (NPTS/QB)         // 128 query tiles
#define TTX    16                // tx groups (target dim)
#define TPT    32                // targets per thread
#define TB     (TTX*TPT)         // 512 targets per block
#define NTT    (NPTS/TB)         // 16 target tiles
#define QSTR   33                // padded stride for q-dir smem reduce (u64s)
#define NBLK2  256

__device__ float g_qpart[NTT][BATCH][NPTS];   // pred-side partial min-s (2MB)
__device__ float g_tpart[NQT][BATCH][NPTS];   // targ-side partial min-s (16.8MB)
__device__ float g_partials[NBLK2];

__device__ __forceinline__ unsigned long long ffma2(unsigned long long a,
                                                    unsigned long long b,
                                                    unsigned long long c) {
    unsigned long long d;
    asm("fma.rn.f32x2 %0, %1, %2, %3;" : "=l"(d) : "l"(a), "l"(b), "l"(c));
    return d;
}
__device__ __forceinline__ unsigned long long mul2(unsigned long long a,
                                                   unsigned long long b) {
    unsigned long long d;
    asm("mul.rn.f32x2 %0, %1, %2;" : "=l"(d) : "l"(a), "l"(b));
    return d;
}
__device__ __forceinline__ unsigned long long add2(unsigned long long a,
                                                   unsigned long long b) {
    unsigned long long d;
    asm("add.rn.f32x2 %0, %1, %2;" : "=l"(d) : "l"(a), "l"(b));
    return d;
}
__device__ __forceinline__ unsigned long long pack2(float lo, float hi) {
    unsigned long long r;
    asm("mov.b64 %0, {%1, %2};" : "=l"(r) : "f"(lo), "f"(hi));
    return r;
}
__device__ __forceinline__ float2 unpack2(unsigned long long v) {
    float2 r;
    asm("mov.b64 {%0, %1}, %2;" : "=f"(r.x), "=f"(r.y) : "l"(v));
    return r;
}

// Block = (query-tile of 64, target-tile of 512, batch). Registers hold two
// DIFFERENT queries per f32x2 (q, q+4): 32 regs of query data instead of 64.
// Smem holds targets lane-DUPLICATED: sD1[t]=(x,x,y,y), sD2[t]=(z,z,h,h).
// One dot product feeds both directions:
//   s_pt = h + c (min over targets -> g_qpart), s_tp = g + c (min over
//   queries -> shfl + smem -> g_tpart),  c = -p.t,  d^2 = |v|^2 + 2s.
__global__ __launch_bounds__(TPB, 8)
void chamfer_pair_kernel(const float* __restrict__ pred,
                         const float* __restrict__ targ) {
    __shared__ float4 sD1[TB];                 // (x,x,y,y)  8KB
    __shared__ float4 sD2[TB];                 // (z,z,h,h)  8KB
    __shared__ unsigned long long sRed[QTY/2 * TB / 2];   // 8KB, dual-purpose

    const int tid = threadIdx.x;
    const int tx  = tid & 15;
    const int ty  = tid >> 4;
    const int qt  = blockIdx.x;   // 0..127
    const int tt  = blockIdx.y;   // 0..15
    const int b   = blockIdx.z;   // 0..3

    const float* P = pred + b * 3 * NPTS;
    const float* T = targ + b * 3 * NPTS;

    // ---- stage 512 targets, duplicated-lane layout (4 per thread) ----
    {
        const float* Tx = T + tt * TB;
        const float* Ty = Tx + NPTS;
        const float* Tz = Tx + 2 * NPTS;
        const int m = tid * 4;
        const float4 x4 = *reinterpret_cast<const float4*>(Tx + m);
        const float4 y4 = *reinterpret_cast<const float4*>(Ty + m);
        const float4 z4 = *reinterpret_cast<const float4*>(Tz + m);
        const float xs[4] = {x4.x, x4.y, x4.z, x4.w};
        const float ys[4] = {y4.x, y4.y, y4.z, y4.w};
        const float zs[4] = {z4.x, z4.y, z4.z, z4.w};
#pragma unroll
        for (int k = 0; k < 4; k++) {
            const float h = 0.5f * (xs[k]*xs[k] + ys[k]*ys[k] + zs[k]*zs[k]);
            sD1[m + k] = make_float4(xs[k], xs[k], ys[k], ys[k]);
            sD2[m + k] = make_float4(zs[k], zs[k], h, h);
        }
    }

    // ---- load 8 queries packed as (q, q+4) ----
    unsigned long long npx[4], npy[4], npz[4], gpk[4];
    float accl[4], acch[4];     // lo half = query qp, hi half = qp+4
#pragma unroll
    for (int qp = 0; qp < 4; qp++) {
        const int i0 = qt * QB + ty * QPT + qp;
        const int i1 = i0 + 4;
        const float x0 = P[i0],            x1 = P[i1];
        const float y0 = P[NPTS + i0],     y1 = P[NPTS + i1];
        const float z0 = P[2*NPTS + i0],   z1 = P[2*NPTS + i1];
        npx[qp] = pack2(-x0, -x1);
        npy[qp] = pack2(-y0, -y1);
        npz[qp] = pack2(-z0, -z1);
        gpk[qp] = pack2(0.5f*(x0*x0 + y0*y0 + z0*z0),
                        0.5f*(x1*x1 + y1*y1 + z1*z1));
        accl[qp] = 1e30f;
        acch[qp] = 1e30f;
    }
    __syncthreads();

    const ulonglong2* D1 = reinterpret_cast<const ulonglong2*>(sD1);
    const ulonglong2* D2 = reinterpret_cast<const ulonglong2*>(sD2);

#pragma unroll 4
    for (int jj = 0; jj < TPT; ++jj) {
        const int j = jj * TTX + tx;       // lane-consecutive: conflict-free
        const ulonglong2 av = D1[j];       // (x,x), (y,y)
        const ulonglong2 bv = D2[j];       // (z,z), (h,h)
        float sl[4], sh[4];
#pragma unroll
        for (int qp = 0; qp < 4; qp++) {
            unsigned long long c = mul2(npx[qp], av.x);   // -p.t (2 queries)
            c = ffma2(npy[qp], av.y, c);
            c = ffma2(npz[qp], bv.x, c);
            const float2 spt = unpack2(add2(bv.y, c));    // h + c (pred side)
            accl[qp] = fminf(accl[qp], spt.x);
            acch[qp] = fminf(acch[qp], spt.y);
            const float2 stp = unpack2(add2(gpk[qp], c)); // g + c (targ side)
            sl[qp] = stp.x;
            sh[qp] = stp.y;
        }
        // min over this thread's 8 queries (depth-3 tree)
        float tmin = fminf(fminf(fminf(sl[0], sh[0]), fminf(sl[1], sh[1])),
                           fminf(fminf(sl[2], sh[2]), fminf(sl[3], sh[3])));
        // combine the two ty's sharing this tx within the warp
        tmin = fminf(tmin, __shfl_xor_sync(0xFFFFFFFFu, tmin, 16));
        if ((ty & 1) == 0)
            reinterpret_cast<float*>(sRed)[(ty >> 1) * TB + j] = tmin;
    }
    __syncthreads();

    // ---- t-direction: reduce the 4 ty-pair copies, write 512 partials ----
    {
        const float* sr = reinterpret_cast<const float*>(sRed);
#pragma unroll
        for (int oo = 0; oo < 4; oo++) {
            const int o = oo * TPB + tid;
            float m = sr[o];
#pragma unroll
            for (int c2 = 1; c2 < 4; c2++) m = fminf(m, sr[c2 * TB + o]);
            g_tpart[qt][b][tt * TB + o] = m;
        }
    }
    __syncthreads();

    // ---- q-direction: stage packed accs (padded), reduce over 16 tx ----
#pragma unroll
    for (int qp = 0; qp < 4; qp++)
        sRed[tx * QSTR + ty * 4 + qp] = pack2(accl[qp], acch[qp]);
    __syncthreads();

    if (tid < 32) {                         // (ty, qp) = tid/4, tid%4
        float2 m = unpack2(sRed[tid]);
#pragma unroll
        for (int t2 = 1; t2 < TTX; t2++) {
            const float2 v = unpack2(sRed[t2 * QSTR + tid]);
            m.x = fminf(m.x, v.x);
            m.y = fminf(m.y, v.y);
        }
        const int ty2 = tid >> 2, qp = tid & 3;
        float* dst = &g_qpart[tt][b][qt * QB + ty2 * QPT + qp];
        dst[0] = m.x;        // query qp
        dst[4] = m.y;        // query qp+4
    }
}

// Combine: min over tiles, d = sqrt(|v|^2 + 2*s_min), deterministic block sums.
__global__ __launch_bounds__(256)
void chamfer_combine(const float* __restrict__ pred,
                     const float* __restrict__ targ) {
    __shared__ float red[8];
    const int tid = threadIdx.x;
    const int gp  = blockIdx.x * 256 + tid;   // 0..65535

    float s, v2;
    if (gp < BATCH * NPTS) {                  // pred side: min over target tiles
        const int b   = gp >> 13;
        const int idx = gp & (NPTS - 1);
        s = g_qpart[0][b][idx];
#pragma unroll
        for (int t = 1; t < NTT; t++) s = fminf(s, g_qpart[t][b][idx]);
        const float* P = pred + b * 3 * NPTS;
        const float x = P[idx], y = P[NPTS + idx], z = P[2 * NPTS + idx];
        v2 = x * x + y * y + z * z;
    } else {                                  // targ side: min over query tiles
        const int g2  = gp - BATCH * NPTS;
        const int b   = g2 >> 13;
        const int idx = g2 & (NPTS - 1);
        s = g_tpart[0][b][idx];
#pragma unroll 8
        for (int t = 1; t < NQT; t++) s = fminf(s, g_tpart[t][b][idx]);
        const float* T = targ + b * 3 * NPTS;
        const float x = T[idx], y = T[NPTS + idx], z = T[2 * NPTS + idx];
        v2 = x * x + y * y + z * z;
    }

    float d = sqrtf(fmaxf(fmaf(2.f, s, v2), 0.f));
#pragma unroll
    for (int off = 16; off > 0; off >>= 1)
        d += __shfl_down_sync(0xFFFFFFFFu, d, off);
    if ((tid & 31) == 0) red[tid >> 5] = d;
    __syncthreads();
    if (tid == 0) {
        float t = 0.f;
#pragma unroll
        for (int w = 0; w < 8; w++) t += red[w];
        g_partials[blockIdx.x] = t;
    }
}

// Deterministic final reduction of the 256 block partials.
__global__ void chamfer_reduce(float* __restrict__ out) {
    __shared__ float red[8];
    const int tid = threadIdx.x;
    float v = g_partials[tid];
#pragma unroll
    for (int off = 16; off > 0; off >>= 1)
        v += __shfl_down_sync(0xFFFFFFFFu, v, off);
    if ((tid & 31) == 0) red[tid >> 5] = v;
    __syncthreads();
    if (tid == 0) {
        float s = 0.f;
#pragma unroll
        for (int w = 0; w < 8; w++) s += red[w];
        out[0] = s * (1.0f / (BATCH * NPTS));
    }
}

extern "C" void kernel_launch(void* const* d_in, const int* in_sizes, int n_in,
                              void* d_out, int out_size) {
    const float* pred = (const float*)d_in[0];
    const float* targ = (const float*)d_in[1];
    float* out = (float*)d_out;

    dim3 grid(NQT, NTT, BATCH);   // 128 x 16 x 4 = 8192 blocks
    chamfer_pair_kernel<<<grid, TPB>>>(pred, targ);
    chamfer_combine<<<NBLK2, 256>>>(pred, targ);
    chamfer_reduce<<<1, 256>>>(out);
}

// round 9
// speedup vs baseline: 1.3279x; 1.3279x over previous
#include <cuda_runtime.h>

#define NPTS   8192
#define BATCH  4
#define TPB    128
#define QTY    8                 // ty groups (query dim)
#define QPT    8                 // queries per thread (lane-duplicated packs)
#define QB     (QTY*QPT)         // 64 queries per block
#define NQT    (NPTS/QB)         // 128 query tiles
#define TTX    16                // tx groups (target dim)
#define TPP    16                // packed target-pairs per thread (32 targets)
#define TB     (TTX*TPP*2)       // 512 targets per block
#define NTT    (NPTS/TB)         // 16 target tiles
#define NPAIR  (TB/2)            // 256 target pairs per block
#define QSTR   (QB+1)            // padded stride for q-dir smem reduce (65)
#define NBLK2  256

__device__ float g_qpart[NTT][BATCH][NPTS];   // pred-side partial min-u (2MB)
__device__ float g_tpart[NQT][BATCH][NPTS];   // targ-side partial min-u (16.8MB)
__device__ float g_partials[NBLK2];

__device__ __forceinline__ unsigned long long ffma2(unsigned long long a,
                                                    unsigned long long b,
                                                    unsigned long long c) {
    unsigned long long d;
    asm("fma.rn.f32x2 %0, %1, %2, %3;" : "=l"(d) : "l"(a), "l"(b), "l"(c));
    return d;
}
__device__ __forceinline__ unsigned long long add2(unsigned long long a,
                                                   unsigned long long b) {
    unsigned long long d;
    asm("add.rn.f32x2 %0, %1, %2;" : "=l"(d) : "l"(a), "l"(b));
    return d;
}
__device__ __forceinline__ unsigned long long pack2(float lo, float hi) {
    unsigned long long r;
    asm("mov.b64 %0, {%1, %2};" : "=l"(r) : "f"(lo), "f"(hi));
    return r;
}
__device__ __forceinline__ float2 unpack2(unsigned long long v) {
    float2 r;
    asm("mov.b64 {%0, %1}, %2;" : "=f"(r.x), "=f"(r.y) : "l"(v));
    return r;
}

// Block = (query-tile of 64, target-tile of 512, batch). One pass computes the
// SYMMETRIC score u = 0.5*d^2 = g + h - p.t per pair (2 targets per f32x2):
//   u chain: ffma2 x3 starting from h (smem), + add2 of g.
//   min over targets -> g_qpart (pred side); min over queries -> g_tpart.
__global__ __launch_bounds__(TPB)
void chamfer_pair_kernel(const float* __restrict__ pred,
                         const float* __restrict__ targ) {
    __shared__ float4 sA[NPAIR];   // (x0,x1, y0,y1) per target pair
    __shared__ float4 sB[NPAIR];   // (z0,z1, h0,h1)
    __shared__ unsigned long long sRed[QTY * NPAIR];   // 16KB reduce buffer

    const int tid = threadIdx.x;
    const int tx  = tid & 15;
    const int ty  = tid >> 4;
    const int qt  = blockIdx.x;   // 0..127
    const int tt  = blockIdx.y;   // 0..15
    const int b   = blockIdx.z;   // 0..3

    const float* P = pred + b * 3 * NPTS;
    const float* T = targ + b * 3 * NPTS;

    // ---- stage this tile's 512 targets (one float4-group per thread) ----
    {
        const float* Tx = T + tt * TB;
        const float* Ty = Tx + NPTS;
        const float* Tz = Tx + 2 * NPTS;
        const int m = tid * 4;
        const float4 x4 = *reinterpret_cast<const float4*>(Tx + m);
        const float4 y4 = *reinterpret_cast<const float4*>(Ty + m);
        const float4 z4 = *reinterpret_cast<const float4*>(Tz + m);
        const float h0 = 0.5f * (x4.x * x4.x + y4.x * y4.x + z4.x * z4.x);
        const float h1 = 0.5f * (x4.y * x4.y + y4.y * y4.y + z4.y * z4.y);
        const float h2 = 0.5f * (x4.z * x4.z + y4.z * y4.z + z4.z * z4.z);
        const float h3 = 0.5f * (x4.w * x4.w + y4.w * y4.w + z4.w * z4.w);
        sA[2 * tid]     = make_float4(x4.x, x4.y, y4.x, y4.y);
        sB[2 * tid]     = make_float4(z4.x, z4.y, h0, h1);
        sA[2 * tid + 1] = make_float4(x4.z, x4.w, y4.z, y4.w);
        sB[2 * tid + 1] = make_float4(z4.z, z4.w, h2, h3);
    }

    // ---- load this thread's 8 register queries (lane-duplicated packs) ----
    unsigned long long npx[QPT], npy[QPT], npz[QPT], gpk[QPT];
    float accl[QPT], acch[QPT];
#pragma unroll
    for (int q = 0; q < QPT; q++) {
        const int idx = qt * QB + ty * QPT + q;
        const float x = P[idx];
        const float y = P[NPTS + idx];
        const float z = P[2 * NPTS + idx];
        npx[q] = pack2(-x, -x);
        npy[q] = pack2(-y, -y);
        npz[q] = pack2(-z, -z);
        const float g = 0.5f * (x * x + y * y + z * z);
        gpk[q] = pack2(g, g);
        accl[q] = 1e30f;
        acch[q] = 1e30f;
    }
    __syncthreads();

    const ulonglong2* A  = reinterpret_cast<const ulonglong2*>(sA);
    const ulonglong2* Bq = reinterpret_cast<const ulonglong2*>(sB);

#pragma unroll
    for (int jj = 0; jj < TPP; ++jj) {
        const int j = jj * TTX + tx;       // lane-consecutive: conflict-free
        const ulonglong2 av = A[j];        // (x0,x1), (y0,y1)
        const ulonglong2 bv = Bq[j];       // (z0,z1), (h0,h1)
        float sl[QPT], sh[QPT];
#pragma unroll
        for (int q = 0; q < QPT; q++) {
            unsigned long long u = ffma2(npx[q], av.x, bv.y);  // h - x.tx
            u = ffma2(npy[q], av.y, u);
            u = ffma2(npz[q], bv.x, u);
            u = add2(gpk[q], u);                // u = g + h - p.t = d^2/2
            const float2 uf = unpack2(u);
            accl[q] = fminf(accl[q], uf.x);     // pred side (per query)
            acch[q] = fminf(acch[q], uf.y);
            sl[q] = uf.x;                       // targ side candidates
            sh[q] = uf.y;
        }
        // tree-min over the 8 queries (depth 3) for each packed target
        const float tml = fminf(fminf(fminf(sl[0], sl[1]), fminf(sl[2], sl[3])),
                                fminf(fminf(sl[4], sl[5]), fminf(sl[6], sl[7])));
        const float tmh = fminf(fminf(fminf(sh[0], sh[1]), fminf(sh[2], sh[3])),
                                fminf(fminf(sh[4], sh[5]), fminf(sh[6], sh[7])));
        sRed[ty * NPAIR + j] = pack2(tml, tmh);   // lane-consecutive STS.64
    }
    __syncthreads();

    // ---- t-direction: min over the 8 ty copies, write 512 partials ----
#pragma unroll
    for (int oo = 0; oo < 2; oo++) {
        const int o = oo * TPB + tid;      // pair index 0..255, lanes consecutive
        float2 m = unpack2(sRed[o]);
#pragma unroll
        for (int t2 = 1; t2 < QTY; t2++) {
            const float2 v = unpack2(sRed[t2 * NPAIR + o]);
            m.x = fminf(m.x, v.x);
            m.y = fminf(m.y, v.y);
        }
        float* dst = &g_tpart[qt][b][tt * TB + 2 * o];   // pair o = targets 2o,2o+1
        dst[0] = m.x;
        dst[1] = m.y;
    }
    __syncthreads();

    // ---- q-direction: stage packed accs (padded stride), min over 16 tx ----
#pragma unroll
    for (int q = 0; q < QPT; q++)
        sRed[tx * QSTR + ty * QPT + q] = pack2(accl[q], acch[q]);
    __syncthreads();

    if (tid < QB) {
        float2 m = unpack2(sRed[tid]);
#pragma unroll
        for (int t2 = 1; t2 < TTX; t2++) {
            const float2 v = unpack2(sRed[t2 * QSTR + tid]);
            m.x = fminf(m.x, v.x);
            m.y = fminf(m.y, v.y);
        }
        g_qpart[tt][b][qt * QB + tid] = fminf(m.x, m.y);
    }
}

// Combine: min over tiles, d = sqrt(2*u_min), deterministic block sums.
// u already contains the full d^2/2 -> no reload of the point coordinates.
__global__ __launch_bounds__(256)
void chamfer_combine(float* __restrict__ dummy) {
    __shared__ float red[8];
    const int tid = threadIdx.x;
    const int gp  = blockIdx.x * 256 + tid;   // 0..65535

    float u;
    if (gp < BATCH * NPTS) {                  // pred side: min over target tiles
        const int b   = gp >> 13;
        const int idx = gp & (NPTS - 1);
        u = g_qpart[0][b][idx];
#pragma unroll
        for (int t = 1; t < NTT; t++) u = fminf(u, g_qpart[t][b][idx]);
    } else {                                  // targ side: min over query tiles
        const int g2  = gp - BATCH * NPTS;
        const int b   = g2 >> 13;
        const int idx = g2 & (NPTS - 1);
        u = g_tpart[0][b][idx];
#pragma unroll 8
        for (int t = 1; t < NQT; t++) u = fminf(u, g_tpart[t][b][idx]);
    }

    float d = sqrtf(fmaxf(2.f * u, 0.f));
#pragma unroll
    for (int off = 16; off > 0; off >>= 1)
        d += __shfl_down_sync(0xFFFFFFFFu, d, off);
    if ((tid & 31) == 0) red[tid >> 5] = d;
    __syncthreads();
    if (tid == 0) {
        float t = 0.f;
#pragma unroll
        for (int w = 0; w < 8; w++) t += red[w];
        g_partials[blockIdx.x] = t;
    }
}

// Deterministic final reduction of the 256 block partials.
__global__ void chamfer_reduce(float* __restrict__ out) {
    __shared__ float red[8];
    const int tid = threadIdx.x;
    float v = g_partials[tid];
#pragma unroll
    for (int off = 16; off > 0; off >>= 1)
        v += __shfl_down_sync(0xFFFFFFFFu, v, off);
    if ((tid & 31) == 0) red[tid >> 5] = v;
    __syncthreads();
    if (tid == 0) {
        float s = 0.f;
#pragma unroll
        for (int w = 0; w < 8; w++) s += red[w];
        out[0] = s * (1.0f / (BATCH * NPTS));
    }
}

extern "C" void kernel_launch(void* const* d_in, const int* in_sizes, int n_in,
                              void* d_out, int out_size) {
    const float* pred = (const float*)d_in[0];
    const float* targ = (const float*)d_in[1];
    float* out = (float*)d_out;

    dim3 grid(NQT, NTT, BATCH);   // 128 x 16 x 4 = 8192 blocks
    chamfer_pair_kernel<<<grid, TPB>>>(pred, targ);
    chamfer_combine<<<NBLK2, 256>>>(out);
    chamfer_reduce<<<1, 256>>>(out);
}

// round 10
// speedup vs baseline: 1.3304x; 1.0019x over previous
#include <cuda_runtime.h>

#define NPTS   8192
#define BATCH  4
#define TPB    128
#define QTY    8                 // ty groups (query dim)
#define QPT    8                 // queries per thread (lane-duplicated packs)
#define QB     (QTY*QPT)         // 64 queries per block
#define NQT    (NPTS/QB)         // 128 query tiles
#define TTX    16                // tx groups (target dim)
#define TPP    16                // packed target-pairs per thread (32 targets)
#define TB     (TTX*TPP*2)       // 512 targets per block
#define NTT    (NPTS/TB)         // 16 target tiles
#define NPAIR  (TB/2)            // 256 target pairs per block
#define QSTR   (QB+1)            // padded stride for q-dir smem reduce (65)
#define NBLK2  256

__device__ float g_qpart[NTT][BATCH][NPTS];   // pred-side partial min-u (2MB)
__device__ float g_tpart[NQT][BATCH][NPTS];   // targ-side partial min-u (16.8MB)
__device__ float g_partials[NBLK2];

__device__ __forceinline__ unsigned long long ffma2(unsigned long long a,
                                                    unsigned long long b,
                                                    unsigned long long c) {
    unsigned long long d;
    asm("fma.rn.f32x2 %0, %1, %2, %3;" : "=l"(d) : "l"(a), "l"(b), "l"(c));
    return d;
}
__device__ __forceinline__ unsigned long long add2(unsigned long long a,
                                                   unsigned long long b) {
    unsigned long long d;
    asm("add.rn.f32x2 %0, %1, %2;" : "=l"(d) : "l"(a), "l"(b));
    return d;
}
__device__ __forceinline__ unsigned long long pack2(float lo, float hi) {
    unsigned long long r;
    asm("mov.b64 %0, {%1, %2};" : "=l"(r) : "f"(lo), "f"(hi));
    return r;
}
__device__ __forceinline__ float2 unpack2(unsigned long long v) {
    float2 r;
    asm("mov.b64 {%0, %1}, %2;" : "=f"(r.x), "=f"(r.y) : "l"(v));
    return r;
}

// Block = (query-tile of 64, target-tile of 512, batch). One pass computes the
// SYMMETRIC score u = 0.5*d^2 = g + h - p.t per pair (2 targets per f32x2):
//   u chain: ffma2 x3 seeded from h (smem), + add2 of g.
//   min over targets -> g_qpart (pred side); min over queries -> g_tpart.
// t-side min uses 4 running chains (even/odd x lo/hi) to keep regs <= 80
// (6 blocks/SM).
__global__ __launch_bounds__(TPB, 6)
void chamfer_pair_kernel(const float* __restrict__ pred,
                         const float* __restrict__ targ) {
    __shared__ float4 sA[NPAIR];   // (x0,x1, y0,y1) per target pair
    __shared__ float4 sB[NPAIR];   // (z0,z1, h0,h1)
    __shared__ unsigned long long sRed[QTY * NPAIR];   // 16KB reduce buffer

    const int tid = threadIdx.x;
    const int tx  = tid & 15;
    const int ty  = tid >> 4;
    const int qt  = blockIdx.x;   // 0..127
    const int tt  = blockIdx.y;   // 0..15
    const int b   = blockIdx.z;   // 0..3

    const float* P = pred + b * 3 * NPTS;
    const float* T = targ + b * 3 * NPTS;

    // ---- stage this tile's 512 targets (one float4-group per thread) ----
    {
        const float* Tx = T + tt * TB;
        const float* Ty = Tx + NPTS;
        const float* Tz = Tx + 2 * NPTS;
        const int m = tid * 4;
        const float4 x4 = *reinterpret_cast<const float4*>(Tx + m);
        const float4 y4 = *reinterpret_cast<const float4*>(Ty + m);
        const float4 z4 = *reinterpret_cast<const float4*>(Tz + m);
        const float h0 = 0.5f * (x4.x * x4.x + y4.x * y4.x + z4.x * z4.x);
        const float h1 = 0.5f * (x4.y * x4.y + y4.y * y4.y + z4.y * z4.y);
        const float h2 = 0.5f * (x4.z * x4.z + y4.z * y4.z + z4.z * z4.z);
        const float h3 = 0.5f * (x4.w * x4.w + y4.w * y4.w + z4.w * z4.w);
        sA[2 * tid]     = make_float4(x4.x, x4.y, y4.x, y4.y);
        sB[2 * tid]     = make_float4(z4.x, z4.y, h0, h1);
        sA[2 * tid + 1] = make_float4(x4.z, x4.w, y4.z, y4.w);
        sB[2 * tid + 1] = make_float4(z4.z, z4.w, h2, h3);
    }

    // ---- load this thread's 8 register queries (lane-duplicated packs) ----
    unsigned long long npx[QPT], npy[QPT], npz[QPT], gpk[QPT];
    float accl[QPT], acch[QPT];
#pragma unroll
    for (int q = 0; q < QPT; q++) {
        const int idx = qt * QB + ty * QPT + q;
        const float x = P[idx];
        const float y = P[NPTS + idx];
        const float z = P[2 * NPTS + idx];
        npx[q] = pack2(-x, -x);
        npy[q] = pack2(-y, -y);
        npz[q] = pack2(-z, -z);
        const float g = 0.5f * (x * x + y * y + z * z);
        gpk[q] = pack2(g, g);
        accl[q] = 1e30f;
        acch[q] = 1e30f;
    }
    __syncthreads();

    const ulonglong2* A  = reinterpret_cast<const ulonglong2*>(sA);
    const ulonglong2* Bq = reinterpret_cast<const ulonglong2*>(sB);

#pragma unroll
    for (int jj = 0; jj < TPP; ++jj) {
        const int j = jj * TTX + tx;       // lane-consecutive: conflict-free
        const ulonglong2 av = A[j];        // (x0,x1), (y0,y1)
        const ulonglong2 bv = Bq[j];       // (z0,z1), (h0,h1)
        float tl0, tl1, th0, th1;          // 4 running t-side chains
#pragma unroll
        for (int q = 0; q < QPT; q++) {
            unsigned long long u = ffma2(npx[q], av.x, bv.y);  // h - x.tx
            u = ffma2(npy[q], av.y, u);
            u = ffma2(npz[q], bv.x, u);
            u = add2(gpk[q], u);                // u = g + h - p.t = d^2/2
            const float2 uf = unpack2(u);
            accl[q] = fminf(accl[q], uf.x);     // pred side (per query)
            acch[q] = fminf(acch[q], uf.y);
            if (q == 0)      { tl0 = uf.x; th0 = uf.y; }
            else if (q == 1) { tl1 = uf.x; th1 = uf.y; }
            else if (q & 1)  { tl1 = fminf(tl1, uf.x); th1 = fminf(th1, uf.y); }
            else             { tl0 = fminf(tl0, uf.x); th0 = fminf(th0, uf.y); }
        }
        sRed[ty * NPAIR + j] = pack2(fminf(tl0, tl1), fminf(th0, th1));
    }
    __syncthreads();

    // ---- t-direction: min over the 8 ty copies, write 512 partials ----
#pragma unroll
    for (int oo = 0; oo < 2; oo++) {
        const int o = oo * TPB + tid;      // pair index 0..255, lanes consecutive
        float2 m = unpack2(sRed[o]);
#pragma unroll
        for (int t2 = 1; t2 < QTY; t2++) {
            const float2 v = unpack2(sRed[t2 * NPAIR + o]);
            m.x = fminf(m.x, v.x);
            m.y = fminf(m.y, v.y);
        }
        float* dst = &g_tpart[qt][b][tt * TB + 2 * o];   // pair o = targets 2o,2o+1
        dst[0] = m.x;
        dst[1] = m.y;
    }
    __syncthreads();

    // ---- q-direction: stage packed accs (padded stride), min over 16 tx ----
#pragma unroll
    for (int q = 0; q < QPT; q++)
        sRed[tx * QSTR + ty * QPT + q] = pack2(accl[q], acch[q]);
    __syncthreads();

    if (tid < QB) {
        float2 m = unpack2(sRed[tid]);
#pragma unroll
        for (int t2 = 1; t2 < TTX; t2++) {
            const float2 v = unpack2(sRed[t2 * QSTR + tid]);
            m.x = fminf(m.x, v.x);
            m.y = fminf(m.y, v.y);
        }
        g_qpart[tt][b][qt * QB + tid] = fminf(m.x, m.y);
    }
}

// Combine: min over tiles, d = sqrt(2*u_min), deterministic block sums.
__global__ __launch_bounds__(256)
void chamfer_combine(float* __restrict__ dummy) {
    __shared__ float red[8];
    const int tid = threadIdx.x;
    const int gp  = blockIdx.x * 256 + tid;   // 0..65535

    float u;
    if (gp < BATCH * NPTS) {                  // pred side: min over target tiles
        const int b   = gp >> 13;
        const int idx = gp & (NPTS - 1);
        u = g_qpart[0][b][idx];
#pragma unroll
        for (int t = 1; t < NTT; t++) u = fminf(u, g_qpart[t][b][idx]);
    } else {                                  // targ side: min over query tiles
        const int g2  = gp - BATCH * NPTS;
        const int b   = g2 >> 13;
        const int idx = g2 & (NPTS - 1);
        u = g_tpart[0][b][idx];
#pragma unroll 8
        for (int t = 1; t < NQT; t++) u = fminf(u, g_tpart[t][b][idx]);
    }

    float d = sqrtf(fmaxf(2.f * u, 0.f));
#pragma unroll
    for (int off = 16; off > 0; off >>= 1)
        d += __shfl_down_sync(0xFFFFFFFFu, d, off);
    if ((tid & 31) == 0) red[tid >> 5] = d;
    __syncthreads();
    if (tid == 0) {
        float t = 0.f;
#pragma unroll
        for (int w = 0; w < 8; w++) t += red[w];
        g_partials[blockIdx.x] = t;
    }
}

// Deterministic final reduction of the 256 block partials.
__global__ void chamfer_reduce(float* __restrict__ out) {
    __shared__ float red[8];
    const int tid = threadIdx.x;
    float v = g_partials[tid];
#pragma unroll
    for (int off = 16; off > 0; off >>= 1)
        v += __shfl_down_sync(0xFFFFFFFFu, v, off);
    if ((tid & 31) == 0) red[tid >> 5] = v;
    __syncthreads();
    if (tid == 0) {
        float s = 0.f;
#pragma unroll
        for (int w = 0; w < 8; w++) s += red[w];
        out[0] = s * (1.0f / (BATCH * NPTS));
    }
}

extern "C" void kernel_launch(void* const* d_in, const int* in_sizes, int n_in,
                              void* d_out, int out_size) {
    const float* pred = (const float*)d_in[0];
    const float* targ = (const float*)d_in[1];
    float* out = (float*)d_out;

    dim3 grid(NQT, NTT, BATCH);   // 128 x 16 x 4 = 8192 blocks
    chamfer_pair_kernel<<<grid, TPB>>>(pred, targ);
    chamfer_combine<<<NBLK2, 256>>>(out);
    chamfer_reduce<<<1, 256>>>(out);
}

// round 11
// speedup vs baseline: 1.3716x; 1.0310x over previous
#include <cuda_runtime.h>

#define NPTS   8192
#define BATCH  4
#define TPB    128
#define QTY    8                 // ty groups (query dim)
#define QPT    8                 // queries per thread (lane-duplicated packs)
#define QB     (QTY*QPT)         // 64 queries per block
#define NQT    (NPTS/QB)         // 128 query tiles
#define TTX    16                // tx groups (target dim)
#define TPP    32                // packed target-pairs per thread (64 targets)
#define TB     (TTX*TPP*2)       // 1024 targets per block
#define NTT    (NPTS/TB)         // 8 target tiles
#define NPAIR  (TB/2)            // 512 target pairs per block
#define NCOPY  (QTY/2)           // 4 sRed copies (warp-folded via shfl)
#define QSTR   (QB+1)            // padded stride for q-dir smem reduce (65)
#define NBLK2  256

__device__ float g_qpart[NTT][BATCH][NPTS];   // pred-side partial min-u (1MB)
__device__ float g_tpart[NQT][BATCH][NPTS];   // targ-side partial min-u (16.8MB)
__device__ float g_partials[NBLK2];

__device__ __forceinline__ unsigned long long ffma2(unsigned long long a,
                                                    unsigned long long b,
                                                    unsigned long long c) {
    unsigned long long d;
    asm("fma.rn.f32x2 %0, %1, %2, %3;" : "=l"(d) : "l"(a), "l"(b), "l"(c));
    return d;
}
__device__ __forceinline__ unsigned long long add2(unsigned long long a,
                                                   unsigned long long b) {
    unsigned long long d;
    asm("add.rn.f32x2 %0, %1, %2;" : "=l"(d) : "l"(a), "l"(b));
    return d;
}
__device__ __forceinline__ unsigned long long pack2(float lo, float hi) {
    unsigned long long r;
    asm("mov.b64 %0, {%1, %2};" : "=l"(r) : "f"(lo), "f"(hi));
    return r;
}
__device__ __forceinline__ float2 unpack2(unsigned long long v) {
    float2 r;
    asm("mov.b64 {%0, %1}, %2;" : "=f"(r.x), "=f"(r.y) : "l"(v));
    return r;
}

// Block = (query-tile of 64, target-tile of 1024, batch). One pass computes
// u = 0.5*d^2 = g + h - p.t per pair (2 targets per f32x2):
//   min over targets -> g_qpart (pred side); min over queries -> g_tpart.
// The two half-warps (ty pairs) fold their t-side mins via shfl before STS,
// so sRed holds 4 copies (16KB); smem total 33KB -> 6 blocks/SM.
__global__ __launch_bounds__(TPB, 6)
void chamfer_pair_kernel(const float* __restrict__ pred,
                         const float* __restrict__ targ) {
    __shared__ float4 sA[NPAIR];   // (x0,x1, y0,y1) per target pair   8KB
    __shared__ float4 sB[NPAIR];   // (z0,z1, h0,h1)                   8KB
    __shared__ unsigned long long sRed[NCOPY * NPAIR];   // 16KB reduce buffer

    const int tid = threadIdx.x;
    const int tx  = tid & 15;
    const int ty  = tid >> 4;
    const int wid = tid >> 5;     // warp id = ty>>1
    const int qt  = blockIdx.x;   // 0..127
    const int tt  = blockIdx.y;   // 0..7
    const int b   = blockIdx.z;   // 0..3

    const float* P = pred + b * 3 * NPTS;
    const float* T = targ + b * 3 * NPTS;

    // ---- stage this tile's 1024 targets (two float4-groups per thread) ----
    {
        const float* Tx = T + tt * TB;
        const float* Ty = Tx + NPTS;
        const float* Tz = Tx + 2 * NPTS;
#pragma unroll
        for (int i = 0; i < 2; i++) {
            const int g4 = tid + i * TPB;       // float4-group 0..255
            const int m  = g4 * 4;
            const float4 x4 = *reinterpret_cast<const float4*>(Tx + m);
            const float4 y4 = *reinterpret_cast<const float4*>(Ty + m);
            const float4 z4 = *reinterpret_cast<const float4*>(Tz + m);
            const float h0 = 0.5f * (x4.x * x4.x + y4.x * y4.x + z4.x * z4.x);
            const float h1 = 0.5f * (x4.y * x4.y + y4.y * y4.y + z4.y * z4.y);
            const float h2 = 0.5f * (x4.z * x4.z + y4.z * y4.z + z4.z * z4.z);
            const float h3 = 0.5f * (x4.w * x4.w + y4.w * y4.w + z4.w * z4.w);
            sA[2 * g4]     = make_float4(x4.x, x4.y, y4.x, y4.y);
            sB[2 * g4]     = make_float4(z4.x, z4.y, h0, h1);
            sA[2 * g4 + 1] = make_float4(x4.z, x4.w, y4.z, y4.w);
            sB[2 * g4 + 1] = make_float4(z4.z, z4.w, h2, h3);
        }
    }

    // ---- load this thread's 8 register queries (lane-duplicated packs) ----
    unsigned long long npx[QPT], npy[QPT], npz[QPT], gpk[QPT];
    float accl[QPT], acch[QPT];
#pragma unroll
    for (int q = 0; q < QPT; q++) {
        const int idx = qt * QB + ty * QPT + q;
        const float x = P[idx];
        const float y = P[NPTS + idx];
        const float z = P[2 * NPTS + idx];
        npx[q] = pack2(-x, -x);
        npy[q] = pack2(-y, -y);
        npz[q] = pack2(-z, -z);
        const float g = 0.5f * (x * x + y * y + z * z);
        gpk[q] = pack2(g, g);
        accl[q] = 1e30f;
        acch[q] = 1e30f;
    }
    __syncthreads();

    const ulonglong2* A  = reinterpret_cast<const ulonglong2*>(sA);
    const ulonglong2* Bq = reinterpret_cast<const ulonglong2*>(sB);

#pragma unroll 8
    for (int jj = 0; jj < TPP; ++jj) {
        const int j = jj * TTX + tx;       // lane-consecutive: conflict-free
        const ulonglong2 av = A[j];        // (x0,x1), (y0,y1)
        const ulonglong2 bv = Bq[j];       // (z0,z1), (h0,h1)
        float tl0, tl1, th0, th1;          // 4 running t-side chains
#pragma unroll
        for (int q = 0; q < QPT; q++) {
            unsigned long long u = ffma2(npx[q], av.x, bv.y);  // h - x.tx
            u = ffma2(npy[q], av.y, u);
            u = ffma2(npz[q], bv.x, u);
            u = add2(gpk[q], u);                // u = g + h - p.t = d^2/2
            const float2 uf = unpack2(u);
            accl[q] = fminf(accl[q], uf.x);     // pred side (per query)
            acch[q] = fminf(acch[q], uf.y);
            if (q == 0)      { tl0 = uf.x; th0 = uf.y; }
            else if (q == 1) { tl1 = uf.x; th1 = uf.y; }
            else if (q & 1)  { tl1 = fminf(tl1, uf.x); th1 = fminf(th1, uf.y); }
            else             { tl0 = fminf(tl0, uf.x); th0 = fminf(th0, uf.y); }
        }
        float tl = fminf(tl0, tl1);
        float th = fminf(th0, th1);
        // fold the two half-warps (ty = 2w, 2w+1) before storing
        tl = fminf(tl, __shfl_xor_sync(0xFFFFFFFFu, tl, 16));
        th = fminf(th, __shfl_xor_sync(0xFFFFFFFFu, th, 16));
        if ((ty & 1) == 0)
            sRed[wid * NPAIR + j] = pack2(tl, th);
    }
    __syncthreads();

    // ---- t-direction: min over the 4 warp copies, write 1024 partials ----
#pragma unroll
    for (int oo = 0; oo < 4; oo++) {
        const int o = oo * TPB + tid;      // pair index 0..511, lanes consecutive
        float2 m = unpack2(sRed[o]);
#pragma unroll
        for (int t2 = 1; t2 < NCOPY; t2++) {
            const float2 v = unpack2(sRed[t2 * NPAIR + o]);
            m.x = fminf(m.x, v.x);
            m.y = fminf(m.y, v.y);
        }
        float* dst = &g_tpart[qt][b][tt * TB + 2 * o];   // pair o = targets 2o,2o+1
        dst[0] = m.x;
        dst[1] = m.y;
    }
    __syncthreads();

    // ---- q-direction: stage packed accs (padded stride), min over 16 tx ----
#pragma unroll
    for (int q = 0; q < QPT; q++)
        sRed[tx * QSTR + ty * QPT + q] = pack2(accl[q], acch[q]);
    __syncthreads();

    if (tid < QB) {
        float2 m = unpack2(sRed[tid]);
#pragma unroll
        for (int t2 = 1; t2 < TTX; t2++) {
            const float2 v = unpack2(sRed[t2 * QSTR + tid]);
            m.x = fminf(m.x, v.x);
            m.y = fminf(m.y, v.y);
        }
        g_qpart[tt][b][qt * QB + tid] = fminf(m.x, m.y);
    }
}

// Combine: min over tiles, d = sqrt(2*u_min), deterministic block sums.
__global__ __launch_bounds__(256)
void chamfer_combine(float* __restrict__ dummy) {
    __shared__ float red[8];
    const int tid = threadIdx.x;
    const int gp  = blockIdx.x * 256 + tid;   // 0..65535

    float u;
    if (gp < BATCH * NPTS) {                  // pred side: min over target tiles
        const int b   = gp >> 13;
        const int idx = gp & (NPTS - 1);
        u = g_qpart[0][b][idx];
#pragma unroll
        for (int t = 1; t < NTT; t++) u = fminf(u, g_qpart[t][b][idx]);
    } else {                                  // targ side: min over query tiles
        const int g2  = gp - BATCH * NPTS;
        const int b   = g2 >> 13;
        const int idx = g2 & (NPTS - 1);
        u = g_tpart[0][b][idx];
#pragma unroll 8
        for (int t = 1; t < NQT; t++) u = fminf(u, g_tpart[t][b][idx]);
    }

    float d = sqrtf(fmaxf(2.f * u, 0.f));
#pragma unroll
    for (int off = 16; off > 0; off >>= 1)
        d += __shfl_down_sync(0xFFFFFFFFu, d, off);
    if ((tid & 31) == 0) red[tid >> 5] = d;
    __syncthreads();
    if (tid == 0) {
        float t = 0.f;
#pragma unroll
        for (int w = 0; w < 8; w++) t += red[w];
        g_partials[blockIdx.x] = t;
    }
}

// Deterministic final reduction of the 256 block partials.
__global__ void chamfer_reduce(float* __restrict__ out) {
    __shared__ float red[8];
    const int tid = threadIdx.x;
    float v = g_partials[tid];
#pragma unroll
    for (int off = 16; off > 0; off >>= 1)
        v += __shfl_down_sync(0xFFFFFFFFu, v, off);
    if ((tid & 31) == 0) red[tid >> 5] = v;
    __syncthreads();
    if (tid == 0) {
        float s = 0.f;
#pragma unroll
        for (int w = 0; w < 8; w++) s += red[w];
        out[0] = s * (1.0f / (BATCH * NPTS));
    }
}

extern "C" void kernel_launch(void* const* d_in, const int* in_sizes, int n_in,
                              void* d_out, int out_size) {
    const float* pred = (const float*)d_in[0];
    const float* targ = (const float*)d_in[1];
    float* out = (float*)d_out;

    dim3 grid(NQT, NTT, BATCH);   // 128 x 8 x 4 = 4096 blocks
    chamfer_pair_kernel<<<grid, TPB>>>(pred, targ);
    chamfer_combine<<<NBLK2, 256>>>(out);
    chamfer_reduce<<<1, 256>>>(out);
}